// round 16
// baseline (speedup 1.0000x reference)
#include <cuda_runtime.h>
#include <cuda_fp16.h>
#include <math.h>

#define NNODES 50000
#define NE     800000
#define NE4    (NE / 4)
#define NEP    (NE + NNODES)
#define DIN    128
#define F1     256
#define DH     64
#define NCLS   6
#define NB     ((NNODES + 1023) / 1024)

typedef unsigned int u32;

// ---------------- scratch ---------------------------------------------------
__device__ __align__(16) int   g_rowptr[NNODES + 1];
__device__ int                 g_cursor[NNODES];
__device__ int                 g_cnt[NNODES];
__device__ int                 g_col[NEP];
__device__ __align__(16) __half g_w1t[F1 * DIN];     // [n][k] fp16
__device__ __align__(16) __half g_w2t[DH * F1];      // [n][k] fp16
__device__ __align__(16) __half g_h1h[(size_t)NNODES * F1];
__device__ __align__(16) __half g_g1h[(size_t)NNODES * F1];
__device__ __align__(16) __half g_h2h[(size_t)NNODES * DH];
__device__ __align__(16) float g_as1[NNODES * 4];
__device__ __align__(16) float g_ad1[NNODES * 4];
__device__ float               g_as2[NNODES];
__device__ float               g_ad2[NNODES];

__device__ __forceinline__ float lrelu(float v) { return v > 0.f ? v : 0.2f * v; }
__device__ __forceinline__ float elu_f(float v) { return v > 0.f ? v : expm1f(v); }
__device__ __forceinline__ u32 smem_u32(const void* p) {
    return (u32)__cvta_generic_to_shared(p);
}

#define LDSM4(r0, r1, r2, r3, addr) \
    asm volatile("ldmatrix.sync.aligned.m8n8.x4.shared.b16 {%0,%1,%2,%3},[%4];" \
                 : "=r"(r0), "=r"(r1), "=r"(r2), "=r"(r3) : "r"(addr))

#define MMA_FP16(cp, a, b0, b1) \
    asm volatile("mma.sync.aligned.m16n8k16.row.col.f32.f16.f16.f32 " \
                 "{%0,%1,%2,%3},{%4,%5,%6,%7},{%8,%9},{%0,%1,%2,%3};" \
                 : "+f"((cp)[0]), "+f"((cp)[1]), "+f"((cp)[2]), "+f"((cp)[3]) \
                 : "r"((a)[0]), "r"((a)[1]), "r"((a)[2]), "r"((a)[3]), \
                   "r"(b0), "r"(b1))

// ---------------- weight conversion -----------------------------------------
__global__ void cvtw_k(const float* __restrict__ W1, const float* __restrict__ W2) {
    int i = blockIdx.x * blockDim.x + threadIdx.x;
    if (i < F1 * DIN) {
        int n = i >> 7, k = i & 127;
        g_w1t[i] = __float2half_rn(W1[k * F1 + n]);
    }
    int j = i - F1 * DIN;
    if (j >= 0 && j < DH * F1) {
        int n = j >> 8, k = j & 255;
        g_w2t[j] = __float2half_rn(W2[k * DH + n]);
    }
}

// ---------------- CSR build ------------------------------------------------
__global__ void hist_k(const int* __restrict__ ei) {
    int i = blockIdx.x * blockDim.x + threadIdx.x;
    if (i >= NE4) return;
    int4 d = ((const int4*)(ei + NE))[i];
    atomicAdd(&g_cnt[d.x], 1);
    atomicAdd(&g_cnt[d.y], 1);
    atomicAdd(&g_cnt[d.z], 1);
    atomicAdd(&g_cnt[d.w], 1);
}

// fused scan: block b computes its global prefix directly, then local scan,
// writes rowptr, places the self-loop, and initializes the cursor.
__global__ void __launch_bounds__(1024) scanAC_k() {
    __shared__ int ws[32];
    __shared__ int pre_s;
    int b = blockIdx.x, tid = threadIdx.x;
    int lane = tid & 31, wid = tid >> 5;

    // part 1: total of (cnt+1) for all elements before this block
    int pre = 0;
    for (int i = tid; i < b * 1024; i += 1024) pre += g_cnt[i] + 1;
    #pragma unroll
    for (int o = 16; o >= 1; o >>= 1) pre += __shfl_xor_sync(0xffffffffu, pre, o);
    if (lane == 0) ws[wid] = pre;
    __syncthreads();
    if (wid == 0) {
        int s = ws[lane];
        #pragma unroll
        for (int o = 16; o >= 1; o >>= 1) s += __shfl_xor_sync(0xffffffffu, s, o);
        if (lane == 0) pre_s = s;
    }
    __syncthreads();
    int boff = pre_s;
    __syncthreads();   // ws reuse barrier

    // part 2: local inclusive scan of (cnt+1)
    int i = b * 1024 + tid;
    int v = (i < NNODES) ? (g_cnt[i] + 1) : 0;
    int x = v;
    #pragma unroll
    for (int o = 1; o < 32; o <<= 1) {
        int y = __shfl_up_sync(0xffffffffu, x, o);
        if (lane >= o) x += y;
    }
    if (lane == 31) ws[wid] = x;
    __syncthreads();
    if (wid == 0) {
        int s = ws[lane];
        int sx = s;
        #pragma unroll
        for (int o = 1; o < 32; o <<= 1) {
            int y = __shfl_up_sync(0xffffffffu, sx, o);
            if (lane >= o) sx += y;
        }
        ws[lane] = sx - s;
    }
    __syncthreads();
    int incl = x + ws[wid] + boff;
    if (i < NNODES) {
        g_rowptr[i + 1] = incl;
        int start = incl - v;
        g_col[start] = i;          // self-loop first
        g_cursor[i] = start + 1;
    }
    if (b == 0 && tid == 0) g_rowptr[0] = 0;
}

__global__ void scat_k(const int* __restrict__ ei) {
    int i = blockIdx.x * blockDim.x + threadIdx.x;
    if (i >= NE4) return;
    int4 s4 = ((const int4*)ei)[i];
    int4 d4 = ((const int4*)(ei + NE))[i];
    int p0 = atomicAdd(&g_cursor[d4.x], 1);
    int p1 = atomicAdd(&g_cursor[d4.y], 1);
    int p2 = atomicAdd(&g_cursor[d4.z], 1);
    int p3 = atomicAdd(&g_cursor[d4.w], 1);
    g_col[p0] = s4.x; g_col[p1] = s4.y;
    g_col[p2] = s4.z; g_col[p3] = s4.w;
}

// -------- GEMM1: fp16 MMA, 128x64 tile, 8 warps (4m x 2n), 3 CTA/SM --------
__global__ void __launch_bounds__(256, 3) gemm1_k(const float* __restrict__ x,
                                                  const float* __restrict__ asrc,
                                                  const float* __restrict__ adst)
{
    constexpr int K = DIN;
    __shared__ __align__(16) __half sA[2][128 * 24];
    __shared__ __align__(16) __half sB[2][64 * 24];
    __shared__ float2 s_red[8][32];

    const int tid = threadIdx.x, lane = tid & 31, w = tid >> 5;
    const int warp_m = (w & 3) * 32, warp_n = (w >> 2) * 32;
    const int bm = blockIdx.y * 128, bn = blockIdx.x * 64;
    const int head = blockIdx.x;

    const int srow = tid >> 1, sch = (tid & 1) * 8;
    const int arow_g = bm + srow;
    const bool aval = arow_g < NNODES;
    const size_t aoffg = (size_t)arow_g * K + sch;        // fp32 x
    const bool bstage = tid < 128;
    const size_t boffg = (size_t)(bn + srow) * K + sch;   // fp16 w1t (srow<64)
    const u32 soff = (u32)(srow * 24 + sch);

    u32 baseA[2] = { smem_u32(sA[0]), smem_u32(sA[1]) };
    u32 baseB[2] = { smem_u32(sB[0]), smem_u32(sB[1]) };

    const int blk = lane >> 3, li = lane & 7;
    const u32 aoff = (u32)((warp_m + ((blk & 1) << 3) + li) * 48 + (((blk >> 1) << 3) << 1));
    const u32 boff = (u32)((warp_n + ((blk >> 1) << 3) + li) * 48 + (((blk & 1) << 3) << 1));

    float c[2][4][4];
    #pragma unroll
    for (int i = 0; i < 2; i++)
        #pragma unroll
        for (int jn = 0; jn < 4; jn++)
            #pragma unroll
            for (int t = 0; t < 4; t++) c[i][jn][t] = 0.f;

    const float4 zf = make_float4(0.f, 0.f, 0.f, 0.f);
    float4 xa, xb;
    uint4 va, vb;

    auto cvt8 = [&](float4 a, float4 b, uint4& o) {
        __half2 h[4];
        h[0] = __floats2half2_rn(a.x, a.y);
        h[1] = __floats2half2_rn(a.z, a.w);
        h[2] = __floats2half2_rn(b.x, b.y);
        h[3] = __floats2half2_rn(b.z, b.w);
        o = *(uint4*)h;
    };

    xa = aval ? *(const float4*)(x + aoffg) : zf;
    xb = aval ? *(const float4*)(x + aoffg + 4) : zf;
    cvt8(xa, xb, va);
    if (bstage) vb = *(const uint4*)(g_w1t + boffg);
    *(uint4*)&sA[0][soff] = va;
    if (bstage) *(uint4*)&sB[0][soff] = vb;

    for (int step = 0; step < 8; step++) {
        __syncthreads();
        if (step < 7) {
            int k0 = (step + 1) * 16;
            xa = aval ? *(const float4*)(x + aoffg + k0) : zf;
            xb = aval ? *(const float4*)(x + aoffg + k0 + 4) : zf;
            if (bstage) vb = *(const uint4*)(g_w1t + boffg + k0);
        }
        int s = step & 1;
        u32 ar[2][4];
        #pragma unroll
        for (int mf = 0; mf < 2; mf++)
            LDSM4(ar[mf][0], ar[mf][1], ar[mf][2], ar[mf][3], baseA[s] + aoff + mf * 768);
        #pragma unroll
        for (int np = 0; np < 2; np++) {
            u32 br[4];
            LDSM4(br[0], br[1], br[2], br[3], baseB[s] + boff + np * 768);
            #pragma unroll
            for (int mf = 0; mf < 2; mf++) {
                MMA_FP16(c[mf][2 * np],     ar[mf], br[0], br[1]);
                MMA_FP16(c[mf][2 * np + 1], ar[mf], br[2], br[3]);
            }
        }
        if (step < 7) {
            int ns = s ^ 1;
            cvt8(xa, xb, va);
            *(uint4*)&sA[ns][soff] = va;
            if (bstage) *(uint4*)&sB[ns][soff] = vb;
        }
    }

    const int q = lane & 3, r = lane >> 2;
    float as_c[4][2], ad_c[4][2];
    #pragma unroll
    for (int nf = 0; nf < 4; nf++) {
        int n0 = bn + warp_n + nf * 8 + 2 * q;
        as_c[nf][0] = asrc[n0]; as_c[nf][1] = asrc[n0 + 1];
        ad_c[nf][0] = adst[n0]; ad_c[nf][1] = adst[n0 + 1];
    }
    float sp[2][2] = {}, dp[2][2] = {};
    #pragma unroll
    for (int mf = 0; mf < 2; mf++) {
        #pragma unroll
        for (int nf = 0; nf < 4; nf++) {
            float* cc = c[mf][nf];
            sp[mf][0] += cc[0] * as_c[nf][0] + cc[1] * as_c[nf][1];
            sp[mf][1] += cc[2] * as_c[nf][0] + cc[3] * as_c[nf][1];
            dp[mf][0] += cc[0] * ad_c[nf][0] + cc[1] * ad_c[nf][1];
            dp[mf][1] += cc[2] * ad_c[nf][0] + cc[3] * ad_c[nf][1];
        }
        #pragma unroll
        for (int h = 0; h < 2; h++) {
            int row = bm + warp_m + mf * 16 + r + h * 8;
            if (row < NNODES) {
                #pragma unroll
                for (int nf = 0; nf < 4; nf++) {
                    __half2 hv = __floats2half2_rn(c[mf][nf][2 * h], c[mf][nf][2 * h + 1]);
                    *(__half2*)&g_h1h[(size_t)row * F1 + bn + warp_n + nf * 8 + 2 * q] = hv;
                }
            }
        }
    }
    #pragma unroll
    for (int o = 1; o <= 2; o <<= 1) {
        #pragma unroll
        for (int mf = 0; mf < 2; mf++)
            #pragma unroll
            for (int h = 0; h < 2; h++) {
                sp[mf][h] += __shfl_xor_sync(0xffffffffu, sp[mf][h], o);
                dp[mf][h] += __shfl_xor_sync(0xffffffffu, dp[mf][h], o);
            }
    }
    if (q == 0) {
        #pragma unroll
        for (int mf = 0; mf < 2; mf++)
            #pragma unroll
            for (int h = 0; h < 2; h++)
                s_red[w][mf * 16 + h * 8 + r] = make_float2(sp[mf][h], dp[mf][h]);
    }
    __syncthreads();
    if (w < 4 && q == 0) {
        #pragma unroll
        for (int mf = 0; mf < 2; mf++)
            #pragma unroll
            for (int h = 0; h < 2; h++) {
                int lr = mf * 16 + h * 8 + r;
                int row = bm + warp_m + lr;
                if (row < NNODES) {
                    float2 a = s_red[w][lr], b = s_red[w + 4][lr];
                    g_as1[4 * row + head] = a.x + b.x;
                    g_ad1[4 * row + head] = a.y + b.y;
                }
            }
    }
}

// -------- GEMM2: fp16 MMA, 128x64 tile, 8 warps (4m x 2n) ------------------
__global__ void __launch_bounds__(256, 2) gemm2_k(const float* __restrict__ asrc,
                                                  const float* __restrict__ adst)
{
    constexpr int K = F1;
    __shared__ __align__(16) __half sA[2][128 * 24];
    __shared__ __align__(16) __half sB[2][64 * 24];
    __shared__ float2 s_red[8][32];

    const int tid = threadIdx.x, lane = tid & 31, w = tid >> 5;
    const int warp_m = (w & 3) * 32, warp_n = (w >> 2) * 32;
    const int bm = blockIdx.x * 128;

    const int srow = tid >> 1, sch = (tid & 1) * 8;
    const int arow_g = bm + srow;
    const bool aval = arow_g < NNODES;
    const size_t aoffg = (size_t)arow_g * K + sch;
    const bool bstage = tid < 128;
    const size_t boffg = (size_t)srow * K + sch;
    const u32 soff = (u32)(srow * 24 + sch);

    u32 baseA[2] = { smem_u32(sA[0]), smem_u32(sA[1]) };
    u32 baseB[2] = { smem_u32(sB[0]), smem_u32(sB[1]) };

    const int blk = lane >> 3, li = lane & 7;
    const u32 aoff = (u32)((warp_m + ((blk & 1) << 3) + li) * 48 + (((blk >> 1) << 3) << 1));
    const u32 boff = (u32)((warp_n + ((blk >> 1) << 3) + li) * 48 + (((blk & 1) << 3) << 1));

    float c[2][4][4];
    #pragma unroll
    for (int i = 0; i < 2; i++)
        #pragma unroll
        for (int jn = 0; jn < 4; jn++)
            #pragma unroll
            for (int t = 0; t < 4; t++) c[i][jn][t] = 0.f;

    const uint4 z4 = make_uint4(0, 0, 0, 0);
    uint4 va, vb;
    va = aval ? *(const uint4*)(g_g1h + aoffg) : z4;
    if (bstage) vb = *(const uint4*)(g_w2t + boffg);
    *(uint4*)&sA[0][soff] = va;
    if (bstage) *(uint4*)&sB[0][soff] = vb;

    for (int step = 0; step < 16; step++) {
        __syncthreads();
        if (step < 15) {
            int k0 = (step + 1) * 16;
            va = aval ? *(const uint4*)(g_g1h + aoffg + k0) : z4;
            if (bstage) vb = *(const uint4*)(g_w2t + boffg + k0);
        }
        int s = step & 1;
        u32 ar[2][4];
        #pragma unroll
        for (int mf = 0; mf < 2; mf++)
            LDSM4(ar[mf][0], ar[mf][1], ar[mf][2], ar[mf][3], baseA[s] + aoff + mf * 768);
        #pragma unroll
        for (int np = 0; np < 2; np++) {
            u32 br[4];
            LDSM4(br[0], br[1], br[2], br[3], baseB[s] + boff + np * 768);
            #pragma unroll
            for (int mf = 0; mf < 2; mf++) {
                MMA_FP16(c[mf][2 * np],     ar[mf], br[0], br[1]);
                MMA_FP16(c[mf][2 * np + 1], ar[mf], br[2], br[3]);
            }
        }
        if (step < 15) {
            int ns = s ^ 1;
            *(uint4*)&sA[ns][soff] = va;
            if (bstage) *(uint4*)&sB[ns][soff] = vb;
        }
    }

    const int q = lane & 3, r = lane >> 2;
    float as_c[4][2], ad_c[4][2];
    #pragma unroll
    for (int nf = 0; nf < 4; nf++) {
        int n0 = warp_n + nf * 8 + 2 * q;
        as_c[nf][0] = asrc[n0]; as_c[nf][1] = asrc[n0 + 1];
        ad_c[nf][0] = adst[n0]; ad_c[nf][1] = adst[n0 + 1];
    }
    float sp[2][2] = {}, dp[2][2] = {};
    #pragma unroll
    for (int mf = 0; mf < 2; mf++) {
        #pragma unroll
        for (int nf = 0; nf < 4; nf++) {
            float* cc = c[mf][nf];
            sp[mf][0] += cc[0] * as_c[nf][0] + cc[1] * as_c[nf][1];
            sp[mf][1] += cc[2] * as_c[nf][0] + cc[3] * as_c[nf][1];
            dp[mf][0] += cc[0] * ad_c[nf][0] + cc[1] * ad_c[nf][1];
            dp[mf][1] += cc[2] * ad_c[nf][0] + cc[3] * ad_c[nf][1];
        }
        #pragma unroll
        for (int h = 0; h < 2; h++) {
            int row = bm + warp_m + mf * 16 + r + h * 8;
            if (row < NNODES) {
                #pragma unroll
                for (int nf = 0; nf < 4; nf++) {
                    __half2 hv = __floats2half2_rn(c[mf][nf][2 * h], c[mf][nf][2 * h + 1]);
                    *(__half2*)&g_h2h[(size_t)row * DH + warp_n + nf * 8 + 2 * q] = hv;
                }
            }
        }
    }
    #pragma unroll
    for (int o = 1; o <= 2; o <<= 1) {
        #pragma unroll
        for (int mf = 0; mf < 2; mf++)
            #pragma unroll
            for (int h = 0; h < 2; h++) {
                sp[mf][h] += __shfl_xor_sync(0xffffffffu, sp[mf][h], o);
                dp[mf][h] += __shfl_xor_sync(0xffffffffu, dp[mf][h], o);
            }
    }
    if (q == 0) {
        #pragma unroll
        for (int mf = 0; mf < 2; mf++)
            #pragma unroll
            for (int h = 0; h < 2; h++)
                s_red[w][mf * 16 + h * 8 + r] = make_float2(sp[mf][h], dp[mf][h]);
    }
    __syncthreads();
    if (w < 4 && q == 0) {
        #pragma unroll
        for (int mf = 0; mf < 2; mf++)
            #pragma unroll
            for (int h = 0; h < 2; h++) {
                int lr = mf * 16 + h * 8 + r;
                int row = bm + warp_m + lr;
                if (row < NNODES) {
                    float2 a = s_red[w][lr], b = s_red[w + 4][lr];
                    g_as2[row] = a.x + b.x;
                    g_ad2[row] = a.y + b.y;
                }
            }
    }
}

// ------- GAT layer 1: single pass, one exp per lane, unroll x8 --------------
__global__ void gat1_k(const float* __restrict__ b1) {
    int gt = blockIdx.x * blockDim.x + threadIdx.x;
    int w = gt >> 5, lane = gt & 31;
    if (w >= NNODES) return;
    int beg = g_rowptr[w], end = g_rowptr[w + 1];
    const int head = lane >> 3;
    const float advh = g_ad1[4 * w + head];

    float S[8] = {0.f, 0.f, 0.f, 0.f, 0.f, 0.f, 0.f, 0.f};
    float z = 0.f;
    const uint4* hp = (const uint4*)g_h1h;
    const float* asp = g_as1;
    int j = beg;
    for (; j + 7 < end; j += 8) {
        int sv[8];
        #pragma unroll
        for (int t = 0; t < 8; t++) sv[t] = g_col[j + t];
        float av[8];
        #pragma unroll
        for (int t = 0; t < 8; t++) av[t] = asp[4 * sv[t] + head];
        uint4 hv[8];
        #pragma unroll
        for (int t = 0; t < 8; t++) hv[t] = hp[(size_t)sv[t] * 32 + lane];
        float pv[8];
        #pragma unroll
        for (int t = 0; t < 8; t++) pv[t] = __expf(lrelu(av[t] + advh));
        #pragma unroll
        for (int t = 0; t < 8; t++) z += pv[t];
        #pragma unroll
        for (int t = 0; t < 8; t++) {
            const __half2* qq = (const __half2*)&hv[t];
            #pragma unroll
            for (int k = 0; k < 4; k++) {
                float2 f = __half22float2(qq[k]);
                S[2 * k]     += pv[t] * f.x;
                S[2 * k + 1] += pv[t] * f.y;
            }
        }
    }
    for (; j < end; j++) {
        int s = g_col[j];
        float a = asp[4 * s + head];
        uint4 hv = hp[(size_t)s * 32 + lane];
        float p = __expf(lrelu(a + advh));
        z += p;
        const __half2* qq = (const __half2*)&hv;
        #pragma unroll
        for (int k = 0; k < 4; k++) {
            float2 f = __half22float2(qq[k]);
            S[2 * k]     += p * f.x;
            S[2 * k + 1] += p * f.y;
        }
    }
    float inv = 1.f / (z + 1e-16f);
    float4 bb1 = ((const float4*)b1)[2 * lane];
    float4 bb2 = ((const float4*)b1)[2 * lane + 1];
    __half2 oh[4];
    oh[0] = __floats2half2_rn(elu_f(S[0] * inv + bb1.x), elu_f(S[1] * inv + bb1.y));
    oh[1] = __floats2half2_rn(elu_f(S[2] * inv + bb1.z), elu_f(S[3] * inv + bb1.w));
    oh[2] = __floats2half2_rn(elu_f(S[4] * inv + bb2.x), elu_f(S[5] * inv + bb2.y));
    oh[3] = __floats2half2_rn(elu_f(S[6] * inv + bb2.z), elu_f(S[7] * inv + bb2.w));
    *(uint4*)&g_g1h[(size_t)w * F1 + 8 * lane] = *(uint4*)oh;
}

// ------- GAT layer 2: single pass + final linear, fp16 h2, unroll x8 --------
__global__ void gat2_k(const float* __restrict__ b2, const float* __restrict__ Wl,
                       const float* __restrict__ bl, float* __restrict__ out) {
    int gt = blockIdx.x * blockDim.x + threadIdx.x;
    int w = gt >> 5, lane = gt & 31;
    if (w >= NNODES) return;
    int beg = g_rowptr[w], end = g_rowptr[w + 1];
    float adv = g_ad2[w];

    float z = 0.f;
    float2 S = make_float2(0.f, 0.f);
    const __half2* h2p = (const __half2*)g_h2h;
    int j = beg;
    for (; j + 7 < end; j += 8) {
        int sv[8];
        #pragma unroll
        for (int t = 0; t < 8; t++) sv[t] = g_col[j + t];
        float ev[8];
        #pragma unroll
        for (int t = 0; t < 8; t++) ev[t] = g_as2[sv[t]];
        __half2 vv[8];
        #pragma unroll
        for (int t = 0; t < 8; t++) vv[t] = h2p[(size_t)sv[t] * 32 + lane];
        #pragma unroll
        for (int t = 0; t < 8; t++) {
            float p = __expf(lrelu(ev[t] + adv));
            z += p;
            float2 f = __half22float2(vv[t]);
            S.x += p * f.x;
            S.y += p * f.y;
        }
    }
    for (; j < end; j++) {
        int s = g_col[j];
        float p = __expf(lrelu(g_as2[s] + adv));
        z += p;
        float2 f = __half22float2(h2p[(size_t)s * 32 + lane]);
        S.x += p * f.x; S.y += p * f.y;
    }
    float inv = 1.f / (z + 1e-16f);
    float2 bb = ((const float2*)b2)[lane];
    float g0 = elu_f(S.x * inv + bb.x);
    float g1 = elu_f(S.y * inv + bb.y);

    float acc[NCLS];
    #pragma unroll
    for (int c = 0; c < NCLS; c++)
        acc[c] = g0 * Wl[(2 * lane) * NCLS + c] + g1 * Wl[(2 * lane + 1) * NCLS + c];
    #pragma unroll
    for (int o = 16; o >= 1; o >>= 1)
        #pragma unroll
        for (int c = 0; c < NCLS; c++)
            acc[c] += __shfl_xor_sync(0xffffffffu, acc[c], o);
    if (lane == 0) {
        #pragma unroll
        for (int c = 0; c < NCLS; c++)
            out[(size_t)w * NCLS + c] = acc[c] + bl[c];
    }
}

// ---------------- launcher --------------------------------------------------
extern "C" void kernel_launch(void* const* d_in, const int* in_sizes, int n_in,
                              void* d_out, int out_size) {
    const float* x     = (const float*)d_in[0];
    const int*   ei    = (const int*)  d_in[1];
    const float* W1    = (const float*)d_in[2];
    const float* asrc1 = (const float*)d_in[3];
    const float* adst1 = (const float*)d_in[4];
    const float* b1    = (const float*)d_in[5];
    const float* W2    = (const float*)d_in[6];
    const float* asrc2 = (const float*)d_in[7];
    const float* adst2 = (const float*)d_in[8];
    const float* b2    = (const float*)d_in[9];
    const float* Wl    = (const float*)d_in[10];
    const float* bl    = (const float*)d_in[11];
    float* out = (float*)d_out;

    static cudaStream_t s2 = nullptr;
    static cudaEvent_t  e_fork = nullptr, e_join = nullptr;
    static void* cnt_addr = nullptr;
    if (s2 == nullptr) {
        cudaStreamCreateWithFlags(&s2, cudaStreamNonBlocking);
        cudaEventCreateWithFlags(&e_fork, cudaEventDisableTiming);
        cudaEventCreateWithFlags(&e_join, cudaEventDisableTiming);
        cudaGetSymbolAddress(&cnt_addr, g_cnt);
    }

    // main stream: weight conversion feeds gemm1
    cvtw_k<<<(F1 * DIN + DH * F1 + 255) / 256, 256>>>(W1, W2);

    // fork: CSR build on side stream
    cudaEventRecord(e_fork, 0);
    cudaStreamWaitEvent(s2, e_fork, 0);
    cudaMemsetAsync(cnt_addr, 0, NNODES * sizeof(int), s2);
    hist_k<<<(NE4 + 255) / 256, 256, 0, s2>>>(ei);
    scanAC_k<<<NB, 1024, 0, s2>>>();
    // main stream: retiled fp16 gemm1 (4th kernel submission -> ncu slot)
    gemm1_k<<<dim3(4, (NNODES + 127) / 128), 256>>>(x, asrc1, adst1);
    scat_k<<<(NE4 + 255) / 256, 256, 0, s2>>>(ei);
    cudaEventRecord(e_join, s2);

    // join: gat1 needs both gemm1 (main) and CSR (s2)
    cudaStreamWaitEvent(0, e_join, 0);
    gat1_k<<<(NNODES * 32 + 255) / 256, 256>>>(b1);
    gemm2_k<<<(NNODES + 127) / 128, 256>>>(asrc2, adst2);
    gat2_k<<<(NNODES * 32 + 255) / 256, 256>>>(b2, Wl, bl, out);
}

// round 17
// speedup vs baseline: 1.0526x; 1.0526x over previous
#include <cuda_runtime.h>
#include <cuda_fp16.h>
#include <math.h>

#define NNODES 50000
#define NE     800000
#define NE4    (NE / 4)
#define NEP    (NE + NNODES)
#define DIN    128
#define F1     256
#define DH     64
#define NCLS   6
#define NB     ((NNODES + 1023) / 1024)

typedef unsigned int u32;

// ---------------- scratch ---------------------------------------------------
__device__ __align__(16) int   g_rowptr[NNODES + 1];
__device__ int                 g_cursor[NNODES];
__device__ int                 g_cnt[NNODES];
__device__ int                 g_col[NEP];
__device__ __align__(16) __half g_w1t[F1 * DIN];     // [n][k] fp16
__device__ __align__(16) __half g_w2t[DH * F1];      // [n][k] fp16
__device__ __align__(16) __half g_h1h[(size_t)NNODES * F1];
__device__ __align__(16) __half g_g1h[(size_t)NNODES * F1];
__device__ __align__(16) __half g_h2h[(size_t)NNODES * DH];
__device__ __align__(16) float g_as1[NNODES * 4];
__device__ __align__(16) float g_ad1[NNODES * 4];
__device__ float               g_as2[NNODES];
__device__ float               g_ad2[NNODES];

__device__ __forceinline__ float lrelu(float v) { return v > 0.f ? v : 0.2f * v; }
__device__ __forceinline__ float elu_f(float v) { return v > 0.f ? v : expm1f(v); }
__device__ __forceinline__ u32 smem_u32(const void* p) {
    return (u32)__cvta_generic_to_shared(p);
}

#define LDSM4(r0, r1, r2, r3, addr) \
    asm volatile("ldmatrix.sync.aligned.m8n8.x4.shared.b16 {%0,%1,%2,%3},[%4];" \
                 : "=r"(r0), "=r"(r1), "=r"(r2), "=r"(r3) : "r"(addr))

#define MMA_FP16(cp, a, b0, b1) \
    asm volatile("mma.sync.aligned.m16n8k16.row.col.f32.f16.f16.f32 " \
                 "{%0,%1,%2,%3},{%4,%5,%6,%7},{%8,%9},{%0,%1,%2,%3};" \
                 : "+f"((cp)[0]), "+f"((cp)[1]), "+f"((cp)[2]), "+f"((cp)[3]) \
                 : "r"((a)[0]), "r"((a)[1]), "r"((a)[2]), "r"((a)[3]), \
                   "r"(b0), "r"(b1))

// ---------------- weight conversion -----------------------------------------
__global__ void cvtw_k(const float* __restrict__ W1, const float* __restrict__ W2) {
    int i = blockIdx.x * blockDim.x + threadIdx.x;
    if (i < F1 * DIN) {
        int n = i >> 7, k = i & 127;
        g_w1t[i] = __float2half_rn(W1[k * F1 + n]);
    }
    int j = i - F1 * DIN;
    if (j >= 0 && j < DH * F1) {
        int n = j >> 8, k = j & 255;
        g_w2t[j] = __float2half_rn(W2[k * DH + n]);
    }
}

// ---------------- CSR build ------------------------------------------------
__global__ void hist_k(const int* __restrict__ ei) {
    int i = blockIdx.x * blockDim.x + threadIdx.x;
    if (i >= NE4) return;
    int4 d = ((const int4*)(ei + NE))[i];
    atomicAdd(&g_cnt[d.x], 1);
    atomicAdd(&g_cnt[d.y], 1);
    atomicAdd(&g_cnt[d.z], 1);
    atomicAdd(&g_cnt[d.w], 1);
}

// fused scan: block b computes its global prefix directly, then local scan,
// writes rowptr, places the self-loop, and initializes the cursor.
__global__ void __launch_bounds__(1024) scanAC_k() {
    __shared__ int ws[32];
    __shared__ int pre_s;
    int b = blockIdx.x, tid = threadIdx.x;
    int lane = tid & 31, wid = tid >> 5;

    // part 1: total of (cnt+1) for all elements before this block
    int pre = 0;
    for (int i = tid; i < b * 1024; i += 1024) pre += g_cnt[i] + 1;
    #pragma unroll
    for (int o = 16; o >= 1; o >>= 1) pre += __shfl_xor_sync(0xffffffffu, pre, o);
    if (lane == 0) ws[wid] = pre;
    __syncthreads();
    if (wid == 0) {
        int s = ws[lane];
        #pragma unroll
        for (int o = 16; o >= 1; o >>= 1) s += __shfl_xor_sync(0xffffffffu, s, o);
        if (lane == 0) pre_s = s;
    }
    __syncthreads();
    int boff = pre_s;
    __syncthreads();   // ws reuse barrier

    // part 2: local inclusive scan of (cnt+1)
    int i = b * 1024 + tid;
    int v = (i < NNODES) ? (g_cnt[i] + 1) : 0;
    int x = v;
    #pragma unroll
    for (int o = 1; o < 32; o <<= 1) {
        int y = __shfl_up_sync(0xffffffffu, x, o);
        if (lane >= o) x += y;
    }
    if (lane == 31) ws[wid] = x;
    __syncthreads();
    if (wid == 0) {
        int s = ws[lane];
        int sx = s;
        #pragma unroll
        for (int o = 1; o < 32; o <<= 1) {
            int y = __shfl_up_sync(0xffffffffu, sx, o);
            if (lane >= o) sx += y;
        }
        ws[lane] = sx - s;
    }
    __syncthreads();
    int incl = x + ws[wid] + boff;
    if (i < NNODES) {
        g_rowptr[i + 1] = incl;
        int start = incl - v;
        g_col[start] = i;          // self-loop first
        g_cursor[i] = start + 1;
    }
    if (b == 0 && tid == 0) g_rowptr[0] = 0;
}

__global__ void scat_k(const int* __restrict__ ei) {
    int i = blockIdx.x * blockDim.x + threadIdx.x;
    if (i >= NE4) return;
    int4 s4 = ((const int4*)ei)[i];
    int4 d4 = ((const int4*)(ei + NE))[i];
    int p0 = atomicAdd(&g_cursor[d4.x], 1);
    int p1 = atomicAdd(&g_cursor[d4.y], 1);
    int p2 = atomicAdd(&g_cursor[d4.z], 1);
    int p3 = atomicAdd(&g_cursor[d4.w], 1);
    g_col[p0] = s4.x; g_col[p1] = s4.y;
    g_col[p2] = s4.z; g_col[p3] = s4.w;
}

// -------- GEMM1: fp16 MMA, 128x128 tile, fused att epilogue (R15-proven) ---
__global__ void __launch_bounds__(256, 2) gemm1_k(const float* __restrict__ x,
                                                  const float* __restrict__ asrc,
                                                  const float* __restrict__ adst)
{
    constexpr int K = DIN;
    __shared__ __align__(16) __half sA[2][128 * 24];
    __shared__ __align__(16) __half sB[2][128 * 24];

    const int tid = threadIdx.x, lane = tid & 31, w = tid >> 5;
    const int warp_m = (w & 3) * 32, warp_n = (w >> 2) * 64;
    const int bm = blockIdx.y * 128, bn = blockIdx.x * 128;

    const int srow = tid >> 1, sch = (tid & 1) * 8;
    const int arow_g = bm + srow;
    const bool aval = arow_g < NNODES;
    const size_t aoffg = (size_t)arow_g * K + sch;
    const size_t boffg = (size_t)(bn + srow) * K + sch;
    const u32 soff = (u32)(srow * 24 + sch);

    u32 baseA[2] = { smem_u32(sA[0]), smem_u32(sA[1]) };
    u32 baseB[2] = { smem_u32(sB[0]), smem_u32(sB[1]) };

    const int blk = lane >> 3, li = lane & 7;
    const u32 aoff = (u32)((warp_m + ((blk & 1) << 3) + li) * 48 + (((blk >> 1) << 3) << 1));
    const u32 boff = (u32)((warp_n + ((blk >> 1) << 3) + li) * 48 + (((blk & 1) << 3) << 1));

    float c[2][8][4];
    #pragma unroll
    for (int i = 0; i < 2; i++)
        #pragma unroll
        for (int jn = 0; jn < 8; jn++)
            #pragma unroll
            for (int q = 0; q < 4; q++) c[i][jn][q] = 0.f;

    const float4 zf = make_float4(0.f, 0.f, 0.f, 0.f);
    float4 xa, xb;
    uint4 va, vb;

    auto cvt8 = [&](float4 a, float4 b, uint4& o) {
        __half2 h[4];
        h[0] = __floats2half2_rn(a.x, a.y);
        h[1] = __floats2half2_rn(a.z, a.w);
        h[2] = __floats2half2_rn(b.x, b.y);
        h[3] = __floats2half2_rn(b.z, b.w);
        o = *(uint4*)h;
    };

    xa = aval ? *(const float4*)(x + aoffg) : zf;
    xb = aval ? *(const float4*)(x + aoffg + 4) : zf;
    cvt8(xa, xb, va);
    vb = *(const uint4*)(g_w1t + boffg);
    *(uint4*)&sA[0][soff] = va;
    *(uint4*)&sB[0][soff] = vb;

    for (int step = 0; step < 8; step++) {
        __syncthreads();
        if (step < 7) {
            int k0 = (step + 1) * 16;
            xa = aval ? *(const float4*)(x + aoffg + k0) : zf;
            xb = aval ? *(const float4*)(x + aoffg + k0 + 4) : zf;
            vb = *(const uint4*)(g_w1t + boffg + k0);
        }
        int s = step & 1;
        u32 ar[2][4];
        #pragma unroll
        for (int mf = 0; mf < 2; mf++)
            LDSM4(ar[mf][0], ar[mf][1], ar[mf][2], ar[mf][3], baseA[s] + aoff + mf * 768);
        #pragma unroll
        for (int np = 0; np < 4; np++) {
            u32 br[4];
            LDSM4(br[0], br[1], br[2], br[3], baseB[s] + boff + np * 768);
            #pragma unroll
            for (int mf = 0; mf < 2; mf++) {
                MMA_FP16(c[mf][2 * np],     ar[mf], br[0], br[1]);
                MMA_FP16(c[mf][2 * np + 1], ar[mf], br[2], br[3]);
            }
        }
        if (step < 7) {
            int ns = s ^ 1;
            cvt8(xa, xb, va);
            *(uint4*)&sA[ns][soff] = va;
            *(uint4*)&sB[ns][soff] = vb;
        }
    }

    const int q = lane & 3, r = lane >> 2;
    const int head = blockIdx.x * 2 + (w >> 2);
    float as_c[8][2], ad_c[8][2];
    #pragma unroll
    for (int nf = 0; nf < 8; nf++) {
        int n0 = bn + warp_n + nf * 8 + 2 * q;
        as_c[nf][0] = asrc[n0]; as_c[nf][1] = asrc[n0 + 1];
        ad_c[nf][0] = adst[n0]; ad_c[nf][1] = adst[n0 + 1];
    }
    float sp[2][2] = {}, dp[2][2] = {};
    #pragma unroll
    for (int mf = 0; mf < 2; mf++) {
        #pragma unroll
        for (int nf = 0; nf < 8; nf++) {
            float* cc = c[mf][nf];
            sp[mf][0] += cc[0] * as_c[nf][0] + cc[1] * as_c[nf][1];
            sp[mf][1] += cc[2] * as_c[nf][0] + cc[3] * as_c[nf][1];
            dp[mf][0] += cc[0] * ad_c[nf][0] + cc[1] * ad_c[nf][1];
            dp[mf][1] += cc[2] * ad_c[nf][0] + cc[3] * ad_c[nf][1];
        }
        #pragma unroll
        for (int h = 0; h < 2; h++) {
            int row = bm + warp_m + mf * 16 + r + h * 8;
            if (row < NNODES) {
                #pragma unroll
                for (int nf = 0; nf < 8; nf++) {
                    __half2 hv = __floats2half2_rn(c[mf][nf][2 * h], c[mf][nf][2 * h + 1]);
                    *(__half2*)&g_h1h[(size_t)row * F1 + bn + warp_n + nf * 8 + 2 * q] = hv;
                }
            }
        }
    }
    #pragma unroll
    for (int o = 1; o <= 2; o <<= 1) {
        #pragma unroll
        for (int mf = 0; mf < 2; mf++)
            #pragma unroll
            for (int h = 0; h < 2; h++) {
                sp[mf][h] += __shfl_xor_sync(0xffffffffu, sp[mf][h], o);
                dp[mf][h] += __shfl_xor_sync(0xffffffffu, dp[mf][h], o);
            }
    }
    if (q == 0) {
        #pragma unroll
        for (int mf = 0; mf < 2; mf++)
            #pragma unroll
            for (int h = 0; h < 2; h++) {
                int row = bm + warp_m + mf * 16 + r + h * 8;
                if (row < NNODES) {
                    g_as1[4 * row + head] = sp[mf][h];
                    g_ad1[4 * row + head] = dp[mf][h];
                }
            }
    }
}

// -------- GEMM2: fp16 MMA, 128x64 tile, 8 warps (4m x 2n) ------------------
__global__ void __launch_bounds__(256, 2) gemm2_k(const float* __restrict__ asrc,
                                                  const float* __restrict__ adst)
{
    constexpr int K = F1;
    __shared__ __align__(16) __half sA[2][128 * 24];
    __shared__ __align__(16) __half sB[2][64 * 24];
    __shared__ float2 s_red[8][32];

    const int tid = threadIdx.x, lane = tid & 31, w = tid >> 5;
    const int warp_m = (w & 3) * 32, warp_n = (w >> 2) * 32;
    const int bm = blockIdx.x * 128;

    const int srow = tid >> 1, sch = (tid & 1) * 8;
    const int arow_g = bm + srow;
    const bool aval = arow_g < NNODES;
    const size_t aoffg = (size_t)arow_g * K + sch;
    const bool bstage = tid < 128;
    const size_t boffg = (size_t)srow * K + sch;
    const u32 soff = (u32)(srow * 24 + sch);

    u32 baseA[2] = { smem_u32(sA[0]), smem_u32(sA[1]) };
    u32 baseB[2] = { smem_u32(sB[0]), smem_u32(sB[1]) };

    const int blk = lane >> 3, li = lane & 7;
    const u32 aoff = (u32)((warp_m + ((blk & 1) << 3) + li) * 48 + (((blk >> 1) << 3) << 1));
    const u32 boff = (u32)((warp_n + ((blk >> 1) << 3) + li) * 48 + (((blk & 1) << 3) << 1));

    float c[2][4][4];
    #pragma unroll
    for (int i = 0; i < 2; i++)
        #pragma unroll
        for (int jn = 0; jn < 4; jn++)
            #pragma unroll
            for (int t = 0; t < 4; t++) c[i][jn][t] = 0.f;

    const uint4 z4 = make_uint4(0, 0, 0, 0);
    uint4 va, vb;
    va = aval ? *(const uint4*)(g_g1h + aoffg) : z4;
    if (bstage) vb = *(const uint4*)(g_w2t + boffg);
    *(uint4*)&sA[0][soff] = va;
    if (bstage) *(uint4*)&sB[0][soff] = vb;

    for (int step = 0; step < 16; step++) {
        __syncthreads();
        if (step < 15) {
            int k0 = (step + 1) * 16;
            va = aval ? *(const uint4*)(g_g1h + aoffg + k0) : z4;
            if (bstage) vb = *(const uint4*)(g_w2t + boffg + k0);
        }
        int s = step & 1;
        u32 ar[2][4];
        #pragma unroll
        for (int mf = 0; mf < 2; mf++)
            LDSM4(ar[mf][0], ar[mf][1], ar[mf][2], ar[mf][3], baseA[s] + aoff + mf * 768);
        #pragma unroll
        for (int np = 0; np < 2; np++) {
            u32 br[4];
            LDSM4(br[0], br[1], br[2], br[3], baseB[s] + boff + np * 768);
            #pragma unroll
            for (int mf = 0; mf < 2; mf++) {
                MMA_FP16(c[mf][2 * np],     ar[mf], br[0], br[1]);
                MMA_FP16(c[mf][2 * np + 1], ar[mf], br[2], br[3]);
            }
        }
        if (step < 15) {
            int ns = s ^ 1;
            *(uint4*)&sA[ns][soff] = va;
            if (bstage) *(uint4*)&sB[ns][soff] = vb;
        }
    }

    const int q = lane & 3, r = lane >> 2;
    float as_c[4][2], ad_c[4][2];
    #pragma unroll
    for (int nf = 0; nf < 4; nf++) {
        int n0 = warp_n + nf * 8 + 2 * q;
        as_c[nf][0] = asrc[n0]; as_c[nf][1] = asrc[n0 + 1];
        ad_c[nf][0] = adst[n0]; ad_c[nf][1] = adst[n0 + 1];
    }
    float sp[2][2] = {}, dp[2][2] = {};
    #pragma unroll
    for (int mf = 0; mf < 2; mf++) {
        #pragma unroll
        for (int nf = 0; nf < 4; nf++) {
            float* cc = c[mf][nf];
            sp[mf][0] += cc[0] * as_c[nf][0] + cc[1] * as_c[nf][1];
            sp[mf][1] += cc[2] * as_c[nf][0] + cc[3] * as_c[nf][1];
            dp[mf][0] += cc[0] * ad_c[nf][0] + cc[1] * ad_c[nf][1];
            dp[mf][1] += cc[2] * ad_c[nf][0] + cc[3] * ad_c[nf][1];
        }
        #pragma unroll
        for (int h = 0; h < 2; h++) {
            int row = bm + warp_m + mf * 16 + r + h * 8;
            if (row < NNODES) {
                #pragma unroll
                for (int nf = 0; nf < 4; nf++) {
                    __half2 hv = __floats2half2_rn(c[mf][nf][2 * h], c[mf][nf][2 * h + 1]);
                    *(__half2*)&g_h2h[(size_t)row * DH + warp_n + nf * 8 + 2 * q] = hv;
                }
            }
        }
    }
    #pragma unroll
    for (int o = 1; o <= 2; o <<= 1) {
        #pragma unroll
        for (int mf = 0; mf < 2; mf++)
            #pragma unroll
            for (int h = 0; h < 2; h++) {
                sp[mf][h] += __shfl_xor_sync(0xffffffffu, sp[mf][h], o);
                dp[mf][h] += __shfl_xor_sync(0xffffffffu, dp[mf][h], o);
            }
    }
    if (q == 0) {
        #pragma unroll
        for (int mf = 0; mf < 2; mf++)
            #pragma unroll
            for (int h = 0; h < 2; h++)
                s_red[w][mf * 16 + h * 8 + r] = make_float2(sp[mf][h], dp[mf][h]);
    }
    __syncthreads();
    if (w < 4 && q == 0) {
        #pragma unroll
        for (int mf = 0; mf < 2; mf++)
            #pragma unroll
            for (int h = 0; h < 2; h++) {
                int lr = mf * 16 + h * 8 + r;
                int row = bm + warp_m + lr;
                if (row < NNODES) {
                    float2 a = s_red[w][lr], b = s_red[w + 4][lr];
                    g_as2[row] = a.x + b.x;
                    g_ad2[row] = a.y + b.y;
                }
            }
    }
}

// ------- GAT layer 1: single pass, one exp per lane, unroll x8 --------------
__global__ void gat1_k(const float* __restrict__ b1) {
    int gt = blockIdx.x * blockDim.x + threadIdx.x;
    int w = gt >> 5, lane = gt & 31;
    if (w >= NNODES) return;
    int beg = g_rowptr[w], end = g_rowptr[w + 1];
    const int head = lane >> 3;
    const float advh = g_ad1[4 * w + head];

    float S[8] = {0.f, 0.f, 0.f, 0.f, 0.f, 0.f, 0.f, 0.f};
    float z = 0.f;
    const uint4* hp = (const uint4*)g_h1h;
    const float* asp = g_as1;
    int j = beg;
    for (; j + 7 < end; j += 8) {
        int sv[8];
        #pragma unroll
        for (int t = 0; t < 8; t++) sv[t] = g_col[j + t];
        float av[8];
        #pragma unroll
        for (int t = 0; t < 8; t++) av[t] = asp[4 * sv[t] + head];
        uint4 hv[8];
        #pragma unroll
        for (int t = 0; t < 8; t++) hv[t] = hp[(size_t)sv[t] * 32 + lane];
        float pv[8];
        #pragma unroll
        for (int t = 0; t < 8; t++) pv[t] = __expf(lrelu(av[t] + advh));
        #pragma unroll
        for (int t = 0; t < 8; t++) z += pv[t];
        #pragma unroll
        for (int t = 0; t < 8; t++) {
            const __half2* qq = (const __half2*)&hv[t];
            #pragma unroll
            for (int k = 0; k < 4; k++) {
                float2 f = __half22float2(qq[k]);
                S[2 * k]     += pv[t] * f.x;
                S[2 * k + 1] += pv[t] * f.y;
            }
        }
    }
    for (; j < end; j++) {
        int s = g_col[j];
        float a = asp[4 * s + head];
        uint4 hv = hp[(size_t)s * 32 + lane];
        float p = __expf(lrelu(a + advh));
        z += p;
        const __half2* qq = (const __half2*)&hv;
        #pragma unroll
        for (int k = 0; k < 4; k++) {
            float2 f = __half22float2(qq[k]);
            S[2 * k]     += p * f.x;
            S[2 * k + 1] += p * f.y;
        }
    }
    float inv = 1.f / (z + 1e-16f);
    float4 bb1 = ((const float4*)b1)[2 * lane];
    float4 bb2 = ((const float4*)b1)[2 * lane + 1];
    __half2 oh[4];
    oh[0] = __floats2half2_rn(elu_f(S[0] * inv + bb1.x), elu_f(S[1] * inv + bb1.y));
    oh[1] = __floats2half2_rn(elu_f(S[2] * inv + bb1.z), elu_f(S[3] * inv + bb1.w));
    oh[2] = __floats2half2_rn(elu_f(S[4] * inv + bb2.x), elu_f(S[5] * inv + bb2.y));
    oh[3] = __floats2half2_rn(elu_f(S[6] * inv + bb2.z), elu_f(S[7] * inv + bb2.w));
    *(uint4*)&g_g1h[(size_t)w * F1 + 8 * lane] = *(uint4*)oh;
}

// ------- GAT layer 2: single pass + final linear, fp16 h2, unroll x8 --------
__global__ void gat2_k(const float* __restrict__ b2, const float* __restrict__ Wl,
                       const float* __restrict__ bl, float* __restrict__ out) {
    int gt = blockIdx.x * blockDim.x + threadIdx.x;
    int w = gt >> 5, lane = gt & 31;
    if (w >= NNODES) return;
    int beg = g_rowptr[w], end = g_rowptr[w + 1];
    float adv = g_ad2[w];

    float z = 0.f;
    float2 S = make_float2(0.f, 0.f);
    const __half2* h2p = (const __half2*)g_h2h;
    int j = beg;
    for (; j + 7 < end; j += 8) {
        int sv[8];
        #pragma unroll
        for (int t = 0; t < 8; t++) sv[t] = g_col[j + t];
        float ev[8];
        #pragma unroll
        for (int t = 0; t < 8; t++) ev[t] = g_as2[sv[t]];
        __half2 vv[8];
        #pragma unroll
        for (int t = 0; t < 8; t++) vv[t] = h2p[(size_t)sv[t] * 32 + lane];
        #pragma unroll
        for (int t = 0; t < 8; t++) {
            float p = __expf(lrelu(ev[t] + adv));
            z += p;
            float2 f = __half22float2(vv[t]);
            S.x += p * f.x;
            S.y += p * f.y;
        }
    }
    for (; j < end; j++) {
        int s = g_col[j];
        float p = __expf(lrelu(g_as2[s] + adv));
        z += p;
        float2 f = __half22float2(h2p[(size_t)s * 32 + lane]);
        S.x += p * f.x; S.y += p * f.y;
    }
    float inv = 1.f / (z + 1e-16f);
    float2 bb = ((const float2*)b2)[lane];
    float g0 = elu_f(S.x * inv + bb.x);
    float g1 = elu_f(S.y * inv + bb.y);

    float acc[NCLS];
    #pragma unroll
    for (int c = 0; c < NCLS; c++)
        acc[c] = g0 * Wl[(2 * lane) * NCLS + c] + g1 * Wl[(2 * lane + 1) * NCLS + c];
    #pragma unroll
    for (int o = 16; o >= 1; o >>= 1)
        #pragma unroll
        for (int c = 0; c < NCLS; c++)
            acc[c] += __shfl_xor_sync(0xffffffffu, acc[c], o);
    if (lane == 0) {
        #pragma unroll
        for (int c = 0; c < NCLS; c++)
            out[(size_t)w * NCLS + c] = acc[c] + bl[c];
    }
}

// ---------------- launcher --------------------------------------------------
extern "C" void kernel_launch(void* const* d_in, const int* in_sizes, int n_in,
                              void* d_out, int out_size) {
    const float* x     = (const float*)d_in[0];
    const int*   ei    = (const int*)  d_in[1];
    const float* W1    = (const float*)d_in[2];
    const float* asrc1 = (const float*)d_in[3];
    const float* adst1 = (const float*)d_in[4];
    const float* b1    = (const float*)d_in[5];
    const float* W2    = (const float*)d_in[6];
    const float* asrc2 = (const float*)d_in[7];
    const float* adst2 = (const float*)d_in[8];
    const float* b2    = (const float*)d_in[9];
    const float* Wl    = (const float*)d_in[10];
    const float* bl    = (const float*)d_in[11];
    float* out = (float*)d_out;

    static cudaStream_t s2 = nullptr;
    static cudaEvent_t  e_fork = nullptr, e_join = nullptr;
    static void* cnt_addr = nullptr;
    if (s2 == nullptr) {
        cudaStreamCreateWithFlags(&s2, cudaStreamNonBlocking);
        cudaEventCreateWithFlags(&e_fork, cudaEventDisableTiming);
        cudaEventCreateWithFlags(&e_join, cudaEventDisableTiming);
        cudaGetSymbolAddress(&cnt_addr, g_cnt);
    }

    // main stream: weight conversion feeds gemm1
    cvtw_k<<<(F1 * DIN + DH * F1 + 255) / 256, 256>>>(W1, W2);

    // fork: CSR build on side stream
    cudaEventRecord(e_fork, 0);
    cudaStreamWaitEvent(s2, e_fork, 0);
    cudaMemsetAsync(cnt_addr, 0, NNODES * sizeof(int), s2);
    hist_k<<<(NE4 + 255) / 256, 256, 0, s2>>>(ei);
    scanAC_k<<<NB, 1024, 0, s2>>>();
    // main stream: 128x128 fp16 gemm1 (4th kernel submission -> ncu slot)
    gemm1_k<<<dim3(2, (NNODES + 127) / 128), 256>>>(x, asrc1, adst1);
    scat_k<<<(NE4 + 255) / 256, 256, 0, s2>>>(ei);
    cudaEventRecord(e_join, s2);

    // join: gat1 needs both gemm1 (main) and CSR (s2)
    cudaStreamWaitEvent(0, e_join, 0);
    gat1_k<<<(NNODES * 32 + 255) / 256, 256>>>(b1);
    gemm2_k<<<(NNODES + 127) / 128, 256>>>(asrc2, adst2);
    gat2_k<<<(NNODES * 32 + 255) / 256, 256>>>(b2, Wl, bl, out);
}